// round 6
// baseline (speedup 1.0000x reference)
#include <cuda_runtime.h>

#define KK 48
#define TT 1024
#define BB 512
#define KBIG (1 << 20)
#define NEG_BIG (-3.0e38f)

typedef unsigned long long ull;

__device__ __forceinline__ ull ffma2(ull a, ull b, ull c) {
    ull d;
    asm("fma.rn.f32x2 %0, %1, %2, %3;" : "=l"(d) : "l"(a), "l"(b), "l"(c));
    return d;
}
__device__ __forceinline__ ull fadd2(ull a, ull b) {
    ull d;
    asm("add.rn.f32x2 %0, %1, %2;" : "=l"(d) : "l"(a), "l"(b));
    return d;
}
__device__ __forceinline__ float hsum2(ull v) {
    float lo, hi;
    asm("mov.b64 {%0, %1}, %2;" : "=f"(lo), "=f"(hi) : "l"(v));
    return lo + hi;
}
__device__ __forceinline__ ull pack2(float lo, float hi) {
    ull d;
    asm("mov.b64 %0, {%1, %2};" : "=l"(d) : "f"(lo), "f"(hi));
    return d;
}

// One warp runs BOTH chains (sup + unsup) of batch b, interleaved.
template <int MODE>
__device__ __forceinline__ void run_pair(
    const int lane, const int b,
    const float* __restrict__ emissions,
    const void* __restrict__ maskv,
    const void* __restrict__ targetv,
    const float* __restrict__ startp,
    const void* __restrict__ sforbv,
    const float* __restrict__ endp,
    const void* __restrict__ eforbv,
    const float* __restrict__ trans,
    const void* __restrict__ forbv,
    float* __restrict__ smS, float* __restrict__ smU,
    float* __restrict__ out) {
    const bool hiv = lane < 16;
    const unsigned FULL = 0xffffffffu;
    const int j0 = lane, j1 = 32 + lane;  // j1 used only when hiv

    const unsigned char* f8 = (const unsigned char*)forbv;
    const unsigned int* f32 = (const unsigned int*)forbv;
#define FRB(x) (MODE ? (f8[x] != 0) : (f32[x] != 0u))

    // ---- build E columns for this lane (exp(trans), 0 if forbidden) ----
    ull e0[24], e1[24];
#pragma unroll
    for (int k = 0; k < 24; k++) {
        const int i0 = 2 * k, i1 = 2 * k + 1;
        float a = FRB(i0 * KK + j0) ? 0.f : __expf(trans[i0 * KK + j0]);
        float bb = FRB(i1 * KK + j0) ? 0.f : __expf(trans[i1 * KK + j0]);
        e0[k] = pack2(a, bb);
        float c = 0.f, dd = 0.f;
        if (hiv) {
            c = FRB(i0 * KK + j1) ? 0.f : __expf(trans[i0 * KK + j1]);
            dd = FRB(i1 * KK + j1) ? 0.f : __expf(trans[i1 * KK + j1]);
        }
        e1[k] = pack2(c, dd);
    }

    // ---- sequence length ----
    int len;
    if (MODE == 1) {
        const unsigned int* mrow =
            reinterpret_cast<const unsigned int*>((const unsigned char*)maskv + (size_t)b * TT);
        int cnt = 0;
#pragma unroll
        for (int k2 = 0; k2 < 8; k2++)
            cnt = __dp4a((int)mrow[lane + k2 * 32], 0x01010101, cnt);
#pragma unroll
        for (int o = 16; o > 0; o >>= 1) cnt += __shfl_xor_sync(FULL, cnt, o);
        len = cnt;
    } else {
        const unsigned int* mrow = (const unsigned int*)maskv + (size_t)b * TT;
        int cnt = 0;
#pragma unroll
        for (int k2 = 0; k2 < 32; k2++) cnt += (mrow[lane + k2 * 32] != 0u) ? 1 : 0;
#pragma unroll
        for (int o = 16; o > 0; o >>= 1) cnt += __shfl_xor_sync(FULL, cnt, o);
        len = cnt;
    }
    const int stop = len - 1;  // len >= 512

    const unsigned char* tg8 = (const unsigned char*)targetv + (MODE ? (size_t)b * TT * KK : 0);
    const unsigned int* tg32 = (const unsigned int*)targetv + (MODE ? 0 : (size_t)b * TT * KK);
    const unsigned char* sf8 = (const unsigned char*)sforbv;
    const unsigned int* sf32 = (const unsigned int*)sforbv;
    const unsigned char* ef8 = (const unsigned char*)eforbv;
    const unsigned int* ef32 = (const unsigned int*)eforbv;
#define TGT(off) (MODE ? (tg8[off] != 0) : (tg32[off] != 0u))
#define SFB(s)   (MODE ? (sf8[s] != 0) : (sf32[s] != 0u))
#define EFB(s)   (MODE ? (ef8[s] != 0) : (ef32[s] != 0u))

    const float* emb = emissions + (size_t)b * TT * KK;

    // ---- t=0 init: v = exp(residual); sup tiers per column ----
    int ds_lo, ds_hi, mks = 0;
    float vs_lo, vs_hi, vu_lo, vu_hi;
    {
        float em0 = emb[j0];
        bool m0 = !TGT(j0);
        bool sf0 = SFB(j0);
        ds_lo = (m0 ? 1 : 0) + (sf0 ? 1 : 0);
        vs_lo = __expf((m0 ? 0.f : em0) + (sf0 ? 0.f : startp[j0]));
        vu_lo = __expf(em0 + startp[j0]);
        if (hiv) {
            float em1 = emb[j1];
            bool m1 = !TGT(j1);
            bool sf1 = SFB(j1);
            ds_hi = (m1 ? 1 : 0) + (sf1 ? 1 : 0);
            vs_hi = __expf((m1 ? 0.f : em1) + (sf1 ? 0.f : startp[j1]));
            vu_hi = __expf(em1 + startp[j1]);
        } else {
            ds_hi = KBIG;
            vs_hi = 0.f;
            vu_hi = 0.f;
        }
    }
    float anc_s = 0.f, anc_u = 0.f;
    float rv_s = 1.f, rv_u = 1.f, lgSs = 0.f, lgSu = 0.f;
    int buf = 0;

    // ---- prefetch ring (rows 1..3) ----
    float rl0, rh0, rl1, rh1, rl2, rh2;
    bool tl0 = true, th0 = true, tl1 = true, th1 = true, tl2 = true, th2 = true;
#define PRELOAD(RL, RH, TL, TH, ROW)                                  \
    {                                                                 \
        const float* er = emb + (size_t)(ROW)*KK;                     \
        RL = er[j0];                                                  \
        RH = hiv ? er[j1] : 0.f;                                      \
        TL = TGT((size_t)(ROW)*KK + j0);                              \
        TH = hiv ? TGT((size_t)(ROW)*KK + j1) : true;                 \
    }
    PRELOAD(rl0, rh0, tl0, th0, 1)
    PRELOAD(rl1, rh1, tl1, th1, 2)
    PRELOAD(rl2, rh2, tl2, th2, 3)

#define STEP(RL, RH, TL, TH, T)                                                  \
    do {                                                                         \
        const float glo = __expf(RL);                                            \
        const float ghi = __expf(RH);                                            \
        const bool mlo = !TL, mhi = !TH;                                         \
        {                                                                        \
            int tn = (T) + 3;                                                    \
            if (tn > stop) tn = stop;                                            \
            PRELOAD(RL, RH, TL, TH, tn)                                          \
        }                                                                        \
        unsigned any0 = __ballot_sync(FULL, (ds_lo == 0) || (hiv && ds_hi == 0));\
        unsigned any1 = __ballot_sync(FULL, (ds_lo == 1) || (hiv && ds_hi == 1));\
        const int m = any0 ? 0 : (any1 ? 1 : 2);                                 \
        mks += m;                                                                \
        float ps_lo = (ds_lo == m) ? vs_lo : 0.f;                                \
        float ps_hi = (hiv && (ds_hi == m)) ? vs_hi : 0.f;                       \
        float* pS = smS + 64 * buf;                                              \
        float* pU = smU + 64 * buf;                                              \
        pS[lane] = ps_lo;                                                        \
        pS[lane + 32] = ps_hi;                                                   \
        pU[lane] = vu_lo;                                                        \
        pU[lane + 32] = vu_hi;                                                   \
        __syncwarp();                                                            \
        float Ss = ps_lo + ps_hi;                                                \
        float Su = vu_lo + vu_hi;                                                \
        _Pragma("unroll") for (int o = 16; o > 0; o >>= 1) {                     \
            Ss += __shfl_xor_sync(FULL, Ss, o);                                  \
            Su += __shfl_xor_sync(FULL, Su, o);                                  \
        }                                                                        \
        ull sa0 = 0, sa1 = 0, sc0 = 0, sc1 = 0;                                  \
        ull ua0 = 0, ua1 = 0, uc0 = 0, uc1 = 0;                                  \
        {                                                                        \
            const ulonglong2* qS = (const ulonglong2*)pS;                        \
            const ulonglong2* qU = (const ulonglong2*)pU;                        \
            _Pragma("unroll") for (int k = 0; k < 12; k++) {                     \
                ulonglong2 a = qS[k];                                            \
                ulonglong2 u = qU[k];                                            \
                sa0 = ffma2(a.x, e0[2 * k], sa0);                                \
                sc0 = ffma2(a.x, e1[2 * k], sc0);                                \
                ua0 = ffma2(u.x, e0[2 * k], ua0);                                \
                uc0 = ffma2(u.x, e1[2 * k], uc0);                                \
                sa1 = ffma2(a.y, e0[2 * k + 1], sa1);                            \
                sc1 = ffma2(a.y, e1[2 * k + 1], sc1);                            \
                ua1 = ffma2(u.y, e0[2 * k + 1], ua1);                            \
                uc1 = ffma2(u.y, e1[2 * k + 1], uc1);                            \
            }                                                                    \
        }                                                                        \
        const float As_lo = hsum2(fadd2(sa0, sa1));                              \
        const float As_hi = hsum2(fadd2(sc0, sc1));                              \
        const float Au_lo = hsum2(fadd2(ua0, ua1));                              \
        const float Au_hi = hsum2(fadd2(uc0, uc1));                              \
        {                                                                        \
            bool pro = !(As_lo > 0.f);                                           \
            ds_lo = (pro ? 1 : 0) + (mlo ? 1 : 0);                               \
            float base = pro ? 1.f : As_lo * rv_s;                               \
            vs_lo = mlo ? base : base * glo;                                     \
        }                                                                        \
        if (hiv) {                                                               \
            bool pro = !(As_hi > 0.f);                                           \
            ds_hi = (pro ? 1 : 0) + (mhi ? 1 : 0);                               \
            float base = pro ? 1.f : As_hi * rv_s;                               \
            vs_hi = mhi ? base : base * ghi;                                     \
        }                                                                        \
        vu_lo = Au_lo * rv_u * glo;                                              \
        vu_hi = Au_hi * rv_u * ghi;                                              \
        anc_s += lgSs;                                                           \
        anc_u += lgSu;                                                           \
        rv_s = __fdividef(1.f, Ss);                                              \
        lgSs = __logf(Ss);                                                       \
        rv_u = __fdividef(1.f, Su);                                              \
        lgSu = __logf(Su);                                                       \
        buf ^= 1;                                                                \
    } while (0)

    int t = 1;
    for (; t + 2 <= stop; t += 3) {
        STEP(rl0, rh0, tl0, th0, t);
        STEP(rl1, rh1, tl1, th1, t + 1);
        STEP(rl2, rh2, tl2, th2, t + 2);
    }
    if (t <= stop) { STEP(rl0, rh0, tl0, th0, t); t++; }
    if (t <= stop) { STEP(rl1, rh1, tl1, th1, t); }

    // ---- epilogue: tiered logsumexp(anc + log v + end) per chain ----
#define TIERED(K0, R0, K1, R1, OUTK, OUTR)                        \
    {                                                             \
        int fk;                                                   \
        float fr;                                                 \
        if ((K0) < (K1)) { fk = (K0); fr = (R0); }                \
        else if ((K1) < (K0)) { fk = (K1); fr = (R1); }           \
        else { fk = (K0); fr = fmaxf((R0), (R1)); }               \
        _Pragma("unroll") for (int o = 16; o > 0; o >>= 1) {      \
            int ok = __shfl_xor_sync(FULL, fk, o);                \
            float orr = __shfl_xor_sync(FULL, fr, o);             \
            if (ok < fk) { fk = ok; fr = orr; }                   \
            else if (ok == fk) fr = fmaxf(fr, orr);               \
        }                                                         \
        float ss = (((K0) == fk) ? __expf((R0)-fr) : 0.f) +       \
                   (((K1) == fk) ? __expf((R1)-fr) : 0.f);        \
        _Pragma("unroll") for (int o = 16; o > 0; o >>= 1)        \
            ss += __shfl_xor_sync(FULL, ss, o);                   \
        OUTK = fk;                                                \
        OUTR = fr + __logf(ss);                                   \
    }

    int zks, zku;
    float zrs, zru;
    {
        bool e0b = EFB(j0);
        int k0 = mks + ds_lo + (e0b ? 1 : 0);
        float r0 = anc_s + __logf(vs_lo) + (e0b ? 0.f : endp[j0]);
        int k1 = KBIG;
        float r1 = NEG_BIG;
        if (hiv) {
            bool e1b = EFB(j1);
            k1 = mks + ds_hi + (e1b ? 1 : 0);
            r1 = anc_s + __logf(vs_hi) + (e1b ? 0.f : endp[j1]);
        }
        TIERED(k0, r0, k1, r1, zks, zrs)
    }
    {
        bool e0b = EFB(j0);
        int k0 = (e0b ? 1 : 0);
        float r0 = anc_u + __logf(vu_lo) + (e0b ? 0.f : endp[j0]);
        int k1 = KBIG;
        float r1 = NEG_BIG;
        if (hiv) {
            bool e1b = EFB(j1);
            k1 = (e1b ? 1 : 0);
            r1 = anc_u + __logf(vu_hi) + (e1b ? 0.f : endp[j1]);
        }
        TIERED(k0, r0, k1, r1, zku, zru)
    }
    if (lane == 0) {
        double v = -1.0e7 * (double)(zku - zks) + (double)(zru - zrs);
        out[b] = (float)v;
    }
#undef FRB
#undef TGT
#undef SFB
#undef EFB
#undef PRELOAD
#undef STEP
#undef TIERED
}

__global__ void __launch_bounds__(32) crf_kernel(
    const float* __restrict__ emissions,
    const void* __restrict__ maskv,
    const void* __restrict__ targetv,
    const float* __restrict__ startp,
    const void* __restrict__ sforbv,
    const float* __restrict__ endp,
    const void* __restrict__ eforbv,
    const float* __restrict__ trans,
    const void* __restrict__ forbv,
    float* __restrict__ out) {
    __shared__ __align__(16) float smS[2 * 64];
    __shared__ __align__(16) float smU[2 * 64];
    const int lane = threadIdx.x;
    const int b = blockIdx.x;
    // mode: bool arrays dumped as bytes (0x01010101) vs 4-byte words
    unsigned w0 = ((const unsigned int*)maskv)[0];
    if (w0 == 0x01010101u)
        run_pair<1>(lane, b, emissions, maskv, targetv, startp, sforbv, endp,
                    eforbv, trans, forbv, smS, smU, out);
    else
        run_pair<0>(lane, b, emissions, maskv, targetv, startp, sforbv, endp,
                    eforbv, trans, forbv, smS, smU, out);
}

extern "C" void kernel_launch(void* const* d_in, const int* in_sizes, int n_in,
                              void* d_out, int out_size) {
    const float* emissions = (const float*)d_in[0];
    const void* mask       = d_in[1];
    const void* target     = d_in[2];
    const float* trans     = (const float*)d_in[3];
    const float* start_t   = (const float*)d_in[4];
    const float* end_t     = (const float*)d_in[5];
    const void* forb       = d_in[6];
    const void* sforb      = d_in[7];
    const void* eforb      = d_in[8];

    crf_kernel<<<BB, 32>>>(emissions, mask, target, start_t, sforb, end_t,
                           eforb, trans, forb, (float*)d_out);
}

// round 7
// speedup vs baseline: 1.0342x; 1.0342x over previous
#include <cuda_runtime.h>

#define KK 48
#define TT 1024
#define BB 512
#define KBIG (1 << 20)
#define NEG_BIG (-3.0e38f)

typedef unsigned long long ull;

__device__ __forceinline__ ull ffma2(ull a, ull b, ull c) {
    ull d;
    asm("fma.rn.f32x2 %0, %1, %2, %3;" : "=l"(d) : "l"(a), "l"(b), "l"(c));
    return d;
}
__device__ __forceinline__ ull fadd2(ull a, ull b) {
    ull d;
    asm("add.rn.f32x2 %0, %1, %2;" : "=l"(d) : "l"(a), "l"(b));
    return d;
}
__device__ __forceinline__ float hsum2(ull v) {
    float lo, hi;
    asm("mov.b64 {%0, %1}, %2;" : "=f"(lo), "=f"(hi) : "l"(v));
    return lo + hi;
}
__device__ __forceinline__ ull pack2(float lo, float hi) {
    ull d;
    asm("mov.b64 %0, {%1, %2};" : "=l"(d) : "f"(lo), "f"(hi));
    return d;
}

// One warp runs BOTH chains (sup + unsup) of batch b, interleaved.
template <int MODE>
__device__ __forceinline__ void run_pair(
    const int lane, const int b,
    const float* __restrict__ emissions,
    const void* __restrict__ maskv,
    const void* __restrict__ targetv,
    const float* __restrict__ startp,
    const void* __restrict__ sforbv,
    const float* __restrict__ endp,
    const void* __restrict__ eforbv,
    const float* __restrict__ trans,
    const void* __restrict__ forbv,
    float* __restrict__ smS, float* __restrict__ smU,
    float* __restrict__ out) {
    const bool hiv = lane < 16;
    const unsigned FULL = 0xffffffffu;
    const int j0 = lane, j1 = 32 + lane;  // j1 valid only when hiv

    const unsigned char* f8 = (const unsigned char*)forbv;
    const unsigned int* f32 = (const unsigned int*)forbv;
#define FRB(x) (MODE ? (f8[x] != 0) : (f32[x] != 0u))

    // ---- build E columns (exp(trans), 0 if forbidden); lane 16 hi = ONES column ----
    ull e0[24], e1[24];
#pragma unroll
    for (int k = 0; k < 24; k++) {
        const int i0 = 2 * k, i1 = 2 * k + 1;
        float a = FRB(i0 * KK + j0) ? 0.f : __expf(trans[i0 * KK + j0]);
        float bb = FRB(i1 * KK + j0) ? 0.f : __expf(trans[i1 * KK + j0]);
        e0[k] = pack2(a, bb);
        float c, dd;
        if (hiv) {
            c = FRB(i0 * KK + j1) ? 0.f : __expf(trans[i0 * KK + j1]);
            dd = FRB(i1 * KK + j1) ? 0.f : __expf(trans[i1 * KK + j1]);
        } else if (lane == 16) {
            c = 1.0f;  // ones column: its matvec result = sum(p) = S
            dd = 1.0f;
        } else {
            c = 0.f;
            dd = 0.f;
        }
        e1[k] = pack2(c, dd);
    }

    // ---- sequence length ----
    int len;
    if (MODE == 1) {
        const unsigned int* mrow =
            reinterpret_cast<const unsigned int*>((const unsigned char*)maskv + (size_t)b * TT);
        int cnt = 0;
#pragma unroll
        for (int k2 = 0; k2 < 8; k2++)
            cnt = __dp4a((int)mrow[lane + k2 * 32], 0x01010101, cnt);
#pragma unroll
        for (int o = 16; o > 0; o >>= 1) cnt += __shfl_xor_sync(FULL, cnt, o);
        len = cnt;
    } else {
        const unsigned int* mrow = (const unsigned int*)maskv + (size_t)b * TT;
        int cnt = 0;
#pragma unroll
        for (int k2 = 0; k2 < 32; k2++) cnt += (mrow[lane + k2 * 32] != 0u) ? 1 : 0;
#pragma unroll
        for (int o = 16; o > 0; o >>= 1) cnt += __shfl_xor_sync(FULL, cnt, o);
        len = cnt;
    }
    const int stop = len - 1;  // len >= 512

    const unsigned char* tg8 = (const unsigned char*)targetv + (MODE ? (size_t)b * TT * KK : 0);
    const unsigned int* tg32 = (const unsigned int*)targetv + (MODE ? 0 : (size_t)b * TT * KK);
    const unsigned char* sf8 = (const unsigned char*)sforbv;
    const unsigned int* sf32 = (const unsigned int*)sforbv;
    const unsigned char* ef8 = (const unsigned char*)eforbv;
    const unsigned int* ef32 = (const unsigned int*)eforbv;
#define TGT(off) (MODE ? (tg8[off] != 0) : (tg32[off] != 0u))
#define SFB(s)   (MODE ? (sf8[s] != 0) : (sf32[s] != 0u))
#define EFB(s)   (MODE ? (ef8[s] != 0) : (ef32[s] != 0u))

    const float* emb = emissions + (size_t)b * TT * KK;

    // ---- t=0 init ----
    int ds_lo, ds_hi, mks = 0;
    float vs_lo, vs_hi, vu_lo, vu_hi;
    {
        float em0 = emb[j0];
        bool m0 = !TGT(j0);
        bool sf0 = SFB(j0);
        ds_lo = (m0 ? 1 : 0) + (sf0 ? 1 : 0);
        vs_lo = __expf((m0 ? 0.f : em0) + (sf0 ? 0.f : startp[j0]));
        vu_lo = __expf(em0 + startp[j0]);
        if (hiv) {
            float em1 = emb[j1];
            bool m1 = !TGT(j1);
            bool sf1 = SFB(j1);
            ds_hi = (m1 ? 1 : 0) + (sf1 ? 1 : 0);
            vs_hi = __expf((m1 ? 0.f : em1) + (sf1 ? 0.f : startp[j1]));
            vu_hi = __expf(em1 + startp[j1]);
        } else {
            ds_hi = KBIG;
            vs_hi = 0.f;
            vu_hi = 0.f;
        }
    }
    bool h0 = (ds_lo == 0) || (hiv && ds_hi == 0);
    bool h1 = (ds_lo == 1) || (hiv && ds_hi == 1);
    float anc_s = 0.f, anc_u = 0.f;
    float rv_s = 1.f, rv_u = 1.f, lgSs = 0.f, lgSu = 0.f;
    int buf = 0;

    // ---- prefetch ring (rows 1..3) ----
    float rl0, rh0, rl1, rh1, rl2, rh2;
    bool tl0 = true, th0 = true, tl1 = true, th1 = true, tl2 = true, th2 = true;
#define PRELOAD(RL, RH, TL, TH, ROW)                                  \
    {                                                                 \
        const float* er = emb + (size_t)(ROW)*KK;                     \
        RL = er[j0];                                                  \
        RH = hiv ? er[j1] : 0.f;                                      \
        TL = TGT((size_t)(ROW)*KK + j0);                              \
        TH = hiv ? TGT((size_t)(ROW)*KK + j1) : true;                 \
    }
    PRELOAD(rl0, rh0, tl0, th0, 1)
    PRELOAD(rl1, rh1, tl1, th1, 2)
    PRELOAD(rl2, rh2, tl2, th2, 3)

#define STEP(RL, RH, TL, TH, T)                                                \
    do {                                                                       \
        const float glo = __expf(RL);                                          \
        const float ghi = __expf(RH);                                          \
        const bool mlo = !TL, mhi = !TH;                                       \
        {                                                                      \
            int tn = (T) + 3;                                                  \
            if (tn > stop) tn = stop;                                          \
            PRELOAD(RL, RH, TL, TH, tn)                                        \
        }                                                                      \
        float* pS = smS + 64 * buf;                                            \
        float* pU = smU + 64 * buf;                                            \
        pU[lane] = vu_lo;                                                      \
        pU[lane + 32] = vu_hi;                                                 \
        unsigned any0 = __ballot_sync(FULL, h0);                               \
        unsigned any1 = __ballot_sync(FULL, h1);                               \
        const int m = any0 ? 0 : (any1 ? 1 : 2);                               \
        mks += m;                                                              \
        float ps_lo = (ds_lo == m) ? vs_lo : 0.f;                              \
        float ps_hi = (hiv && (ds_hi == m)) ? vs_hi : 0.f;                     \
        pS[lane] = ps_lo;                                                      \
        pS[lane + 32] = ps_hi;                                                 \
        __syncwarp();                                                          \
        ull sa0 = 0, sa1 = 0, sc0 = 0, sc1 = 0;                                \
        ull ua0 = 0, ua1 = 0, uc0 = 0, uc1 = 0;                                \
        {                                                                      \
            const ulonglong2* qS = (const ulonglong2*)pS;                      \
            const ulonglong2* qU = (const ulonglong2*)pU;                      \
            ulonglong2 xs[12];                                                 \
            _Pragma("unroll") for (int k = 0; k < 12; k++) xs[k] = qS[k];      \
            _Pragma("unroll") for (int k = 0; k < 12; k++) {                   \
                sa0 = ffma2(xs[k].x, e0[2 * k], sa0);                          \
                sc0 = ffma2(xs[k].x, e1[2 * k], sc0);                          \
                sa1 = ffma2(xs[k].y, e0[2 * k + 1], sa1);                      \
                sc1 = ffma2(xs[k].y, e1[2 * k + 1], sc1);                      \
            }                                                                  \
            _Pragma("unroll") for (int k = 0; k < 12; k++) xs[k] = qU[k];      \
            _Pragma("unroll") for (int k = 0; k < 12; k++) {                   \
                ua0 = ffma2(xs[k].x, e0[2 * k], ua0);                          \
                uc0 = ffma2(xs[k].x, e1[2 * k], uc0);                          \
                ua1 = ffma2(xs[k].y, e0[2 * k + 1], ua1);                      \
                uc1 = ffma2(xs[k].y, e1[2 * k + 1], uc1);                      \
            }                                                                  \
        }                                                                      \
        const float As_lo = hsum2(fadd2(sa0, sa1));                            \
        const float As_hi = hsum2(fadd2(sc0, sc1));                            \
        const float Au_lo = hsum2(fadd2(ua0, ua1));                            \
        const float Au_hi = hsum2(fadd2(uc0, uc1));                            \
        const float SsN = __shfl_sync(FULL, As_hi, 16);                        \
        const float SuN = __shfl_sync(FULL, Au_hi, 16);                        \
        {                                                                      \
            bool pro = !(As_lo > 0.f);                                         \
            ds_lo = (pro ? 1 : 0) + (mlo ? 1 : 0);                             \
            float base = pro ? 1.f : As_lo * rv_s;                             \
            vs_lo = mlo ? base : base * glo;                                   \
        }                                                                      \
        vu_lo = Au_lo * rv_u * glo;                                            \
        if (hiv) {                                                             \
            bool pro = !(As_hi > 0.f);                                         \
            ds_hi = (pro ? 1 : 0) + (mhi ? 1 : 0);                             \
            float base = pro ? 1.f : As_hi * rv_s;                             \
            vs_hi = mhi ? base : base * ghi;                                   \
            vu_hi = Au_hi * rv_u * ghi;                                        \
        }                                                                      \
        h0 = (ds_lo == 0) || (hiv && ds_hi == 0);                              \
        h1 = (ds_lo == 1) || (hiv && ds_hi == 1);                              \
        anc_s += lgSs;                                                         \
        anc_u += lgSu;                                                         \
        rv_s = __fdividef(1.f, SsN);                                           \
        lgSs = __logf(SsN);                                                    \
        rv_u = __fdividef(1.f, SuN);                                           \
        lgSu = __logf(SuN);                                                    \
        buf ^= 1;                                                              \
    } while (0)

    int t = 1;
    for (; t + 2 <= stop; t += 3) {
        STEP(rl0, rh0, tl0, th0, t);
        STEP(rl1, rh1, tl1, th1, t + 1);
        STEP(rl2, rh2, tl2, th2, t + 2);
    }
    if (t <= stop) { STEP(rl0, rh0, tl0, th0, t); t++; }
    if (t <= stop) { STEP(rl1, rh1, tl1, th1, t); }

    // ---- epilogue: tiered logsumexp(anc + log v + end) per chain ----
#define TIERED(K0, R0, K1, R1, OUTK, OUTR)                        \
    {                                                             \
        int fk;                                                   \
        float fr;                                                 \
        if ((K0) < (K1)) { fk = (K0); fr = (R0); }                \
        else if ((K1) < (K0)) { fk = (K1); fr = (R1); }           \
        else { fk = (K0); fr = fmaxf((R0), (R1)); }               \
        _Pragma("unroll") for (int o = 16; o > 0; o >>= 1) {      \
            int ok = __shfl_xor_sync(FULL, fk, o);                \
            float orr = __shfl_xor_sync(FULL, fr, o);             \
            if (ok < fk) { fk = ok; fr = orr; }                   \
            else if (ok == fk) fr = fmaxf(fr, orr);               \
        }                                                         \
        float ss = (((K0) == fk) ? __expf((R0)-fr) : 0.f) +       \
                   (((K1) == fk) ? __expf((R1)-fr) : 0.f);        \
        _Pragma("unroll") for (int o = 16; o > 0; o >>= 1)        \
            ss += __shfl_xor_sync(FULL, ss, o);                   \
        OUTK = fk;                                                \
        OUTR = fr + __logf(ss);                                   \
    }

    int zks, zku;
    float zrs, zru;
    {
        bool e0b = EFB(j0);
        int k0 = mks + ds_lo + (e0b ? 1 : 0);
        float r0 = anc_s + __logf(vs_lo) + (e0b ? 0.f : endp[j0]);
        int k1 = KBIG;
        float r1 = NEG_BIG;
        if (hiv) {
            bool e1b = EFB(j1);
            k1 = mks + ds_hi + (e1b ? 1 : 0);
            r1 = anc_s + __logf(vs_hi) + (e1b ? 0.f : endp[j1]);
        }
        TIERED(k0, r0, k1, r1, zks, zrs)
    }
    {
        bool e0b = EFB(j0);
        int k0 = (e0b ? 1 : 0);
        float r0 = anc_u + __logf(vu_lo) + (e0b ? 0.f : endp[j0]);
        int k1 = KBIG;
        float r1 = NEG_BIG;
        if (hiv) {
            bool e1b = EFB(j1);
            k1 = (e1b ? 1 : 0);
            r1 = anc_u + __logf(vu_hi) + (e1b ? 0.f : endp[j1]);
        }
        TIERED(k0, r0, k1, r1, zku, zru)
    }
    if (lane == 0) {
        double v = -1.0e7 * (double)(zku - zks) + (double)(zru - zrs);
        out[b] = (float)v;
    }
#undef FRB
#undef TGT
#undef SFB
#undef EFB
#undef PRELOAD
#undef STEP
#undef TIERED
}

__global__ void __launch_bounds__(32) crf_kernel(
    const float* __restrict__ emissions,
    const void* __restrict__ maskv,
    const void* __restrict__ targetv,
    const float* __restrict__ startp,
    const void* __restrict__ sforbv,
    const float* __restrict__ endp,
    const void* __restrict__ eforbv,
    const float* __restrict__ trans,
    const void* __restrict__ forbv,
    float* __restrict__ out) {
    __shared__ __align__(16) float smS[2 * 64];
    __shared__ __align__(16) float smU[2 * 64];
    const int lane = threadIdx.x;
    const int b = blockIdx.x;
    unsigned w0 = ((const unsigned int*)maskv)[0];
    if (w0 == 0x01010101u)
        run_pair<1>(lane, b, emissions, maskv, targetv, startp, sforbv, endp,
                    eforbv, trans, forbv, smS, smU, out);
    else
        run_pair<0>(lane, b, emissions, maskv, targetv, startp, sforbv, endp,
                    eforbv, trans, forbv, smS, smU, out);
}

extern "C" void kernel_launch(void* const* d_in, const int* in_sizes, int n_in,
                              void* d_out, int out_size) {
    const float* emissions = (const float*)d_in[0];
    const void* mask       = d_in[1];
    const void* target     = d_in[2];
    const float* trans     = (const float*)d_in[3];
    const float* start_t   = (const float*)d_in[4];
    const float* end_t     = (const float*)d_in[5];
    const void* forb       = d_in[6];
    const void* sforb      = d_in[7];
    const void* eforb      = d_in[8];

    crf_kernel<<<BB, 32>>>(emissions, mask, target, start_t, sforb, end_t,
                           eforb, trans, forb, (float*)d_out);
}